// round 8
// baseline (speedup 1.0000x reference)
#include <cuda_runtime.h>

// CIN (xDeepFM) fused 2-layer kernel, round 8 — transposed mma.sync tf32.
// B=4096, F=32, D=32, layers [128,128].
//
// Transposed GEMM per batch: out'[n][d] = sum_k W[k][n] * z[k][d]
//   layer0: z[k=h*32+m][d]  = u[h][d]*u[m][d],            K=1024
//   layer1: z[k=h*128+m][d] = u[h][d]*relu(cur0)[m][d],   K=4096
// mma.sync.m16n8k8 tf32: A = W^T (n-rows x k), B = z (k x d-cols), fp32 acc.
// Single-term: both operands rna-rounded to tf32 (predicted rel_err ~2e-4).
//
// W is pre-transposed / tf32-rounded / k-permuted / bank-rotated into
// __device__ scratch by a prep kernel (one-time); the mainloop copies each
// 16KB chunk with coalesced LDG.128 + conflict-free STS.128.
// CTA = 4 batches, 256 threads, 8 warps = (batch-pair) x (n-block of 32).

typedef unsigned int u32;

// [chunk c][n 0..127][32]: element (sp,g,e) at group (4sp+g+4n)&7, holds
// W[c*32 + sp*16 + g + 4e][n] rounded to tf32.
__device__ float g_wp[160 * 4096];

namespace {
constexpr int NT    = 256;
constexpr int L0CH  = 32;                  // layer-0 chunks
constexpr int NCH   = 160;                 // total chunks
constexpr int UPSTR = 52;                  // Up row stride (13 float4)
constexpr int UP_SZ = 32 * UPSTR;          // 1664 floats / batch
constexpr int C0_SZ = 32 * 128;            // 4096 floats / batch (rotated rows)
constexpr int UP_OFF = 0;
constexpr int C0_OFF = 4 * UP_SZ;          // 6656
constexpr int WT_OFF = C0_OFF + 4 * C0_SZ; // 23040
constexpr int SMEM_F = WT_OFF + 4096;      // 27136 floats = 106 KB
}

__device__ __forceinline__ u32 cvt_tf32(float x) {
    u32 h;
    asm("cvt.rna.tf32.f32 %0, %1;" : "=r"(h) : "f"(x));
    return h;
}
// permuted position of k within a 32-chunk: float4 groups hold {k,k+4,k+8,k+12}
__device__ __forceinline__ int posk(int k) {
    return ((k >> 4) << 4) | ((k & 3) << 2) | (((k >> 3) & 1) << 1) | ((k >> 2) & 1);
}

// D(16x8) += A(16x8,tf32,row) * B(8x8,tf32,col), fp32 accum.
__device__ __forceinline__ void mma8(float* d, const u32* a, const u32* b) {
    asm volatile(
        "mma.sync.aligned.m16n8k8.row.col.f32.tf32.tf32.f32 "
        "{%0,%1,%2,%3}, {%4,%5,%6,%7}, {%8,%9}, {%0,%1,%2,%3};"
        : "+f"(d[0]), "+f"(d[1]), "+f"(d[2]), "+f"(d[3])
        : "r"(a[0]), "r"(a[1]), "r"(a[2]), "r"(a[3]), "r"(b[0]), "r"(b[1]));
}

// ---- prep: W [k][n] -> g_wp [c][n][perm+rotated], tf32-rounded ------------
__global__ __launch_bounds__(128) void cin_prep(const float* __restrict__ w0,
                                                const float* __restrict__ w1) {
    const int c = blockIdx.x, n = threadIdx.x;
    const float* W = (c < L0CH) ? (w0 + (size_t)c * 4096)
                                : (w1 + (size_t)(c - L0CH) * 4096);
    float v[32];
    #pragma unroll
    for (int k = 0; k < 32; ++k)
        v[k] = __uint_as_float(cvt_tf32(W[k * 128 + n]));
    float* dst = g_wp + (size_t)c * 4096 + n * 32;
    #pragma unroll
    for (int sp = 0; sp < 2; ++sp)
        #pragma unroll
        for (int g = 0; g < 4; ++g) {
            const int pg = (4 * sp + g + 4 * n) & 7;
            *reinterpret_cast<float4*>(dst + pg * 4) =
                make_float4(v[sp * 16 + g], v[sp * 16 + g + 4],
                            v[sp * 16 + g + 8], v[sp * 16 + g + 12]);
        }
}

// ---- main ------------------------------------------------------------------
__global__ __launch_bounds__(NT, 2) void cin_main(const float* __restrict__ x,
                                                  float* __restrict__ out) {
    extern __shared__ __align__(16) float sm[];
    float* const Up = sm + UP_OFF;   // [b][d*52 + posk(m)]  (= transposed u)
    float* const C0 = sm + C0_OFF;   // [b][d*128 + rotated-perm m]
    float* const Wt = sm + WT_OFF;   // [n*32 + rotated perm k]

    const int t    = threadIdx.x;
    const int lane = t & 31;
    const int wid  = t >> 5;
    const int bp   = wid >> 2;       // batch-pair
    const int wn   = wid & 3;        // n-block: n in [32wn, 32wn+32)
    const int lq   = lane >> 2;
    const int lr   = lane & 3;

    // Up init: x[b][h][d] -> Up[b][d][posk(h)]
    for (int i = t; i < 4096; i += NT) {
        const int b = i >> 10, r = i & 1023, h = r >> 5, d = r & 31;
        Up[b * UP_SZ + d * UPSTR + posk(h)] = x[(size_t)blockIdx.x * 4096 + i];
    }

    float acc[2][2][4][4];   // [nt][bb][dt][c0..c3]
    #pragma unroll
    for (int a = 0; a < 2; ++a)
        #pragma unroll
        for (int b = 0; b < 2; ++b)
            #pragma unroll
            for (int d = 0; d < 4; ++d)
                #pragma unroll
                for (int r = 0; r < 4; ++r) acc[a][b][d][r] = 0.f;

    float4 wreg[4];
    {
        const float4* s4 = reinterpret_cast<const float4*>(g_wp);
        #pragma unroll
        for (int j = 0; j < 4; ++j) wreg[j] = s4[t + j * 256];
    }

    for (int c = 0; c < NCH; ++c) {
        __syncthreads();   // all warps done reading Wt(c-1) (and Up init at c=0)
        {
            float4* d4 = reinterpret_cast<float4*>(Wt);
            #pragma unroll
            for (int j = 0; j < 4; ++j) d4[t + j * 256] = wreg[j];
        }

        // ---- layer boundary: epilogue 0 (between the two syncs) ----
        if (c == L0CH) {
            #pragma unroll
            for (int bb = 0; bb < 2; ++bb) {
                const int bidx = bp * 2 + bb;
                const size_t bg = (size_t)blockIdx.x * 4 + bidx;
                float* const Cb = C0 + bidx * C0_SZ;
                #pragma unroll
                for (int nt = 0; nt < 2; ++nt) {
                    float srow[2] = {0.f, 0.f};
                    #pragma unroll
                    for (int dt = 0; dt < 4; ++dt)
                        #pragma unroll
                        for (int cc = 0; cc < 4; ++cc) {
                            const float v = fmaxf(acc[nt][bb][dt][cc], 0.f);
                            const int rh = cc >> 1;
                            const int d  = dt * 8 + 2 * lr + (cc & 1);
                            const int kl = nt * 16 + lq + 8 * rh;
                            const int lp = wn * 32 + posk(kl);
                            Cb[d * 128 + ((((lp >> 2) + 4 * d) & 31) << 2) + (lp & 3)] = v;
                            srow[rh] += v;
                        }
                    #pragma unroll
                    for (int o = 1; o < 4; o <<= 1) {
                        srow[0] += __shfl_xor_sync(0xffffffffu, srow[0], o);
                        srow[1] += __shfl_xor_sync(0xffffffffu, srow[1], o);
                    }
                    if (lr == 0) {
                        const int n = wn * 32 + nt * 16 + lq;
                        out[bg * 256 + n]     = srow[0];
                        out[bg * 256 + n + 8] = srow[1];
                    }
                }
            }
            #pragma unroll
            for (int a = 0; a < 2; ++a)
                #pragma unroll
                for (int b = 0; b < 2; ++b)
                    #pragma unroll
                    for (int d = 0; d < 4; ++d)
                        #pragma unroll
                        for (int r = 0; r < 4; ++r) acc[a][b][d][r] = 0.f;
        }
        __syncthreads();   // Wt(c) (and C0 at c=32) published

        if (c + 1 < NCH) {   // prefetch next W chunk (hidden by compute)
            const float4* s4 =
                reinterpret_cast<const float4*>(g_wp + (size_t)(c + 1) * 4096);
            #pragma unroll
            for (int j = 0; j < 4; ++j) wreg[j] = s4[t + j * 256];
        }

        // ---- per-chunk P operand selection ----
        const bool l0 = (c < L0CH);
        const float* Pb;
        int mb, h;
        if (l0) { Pb = Up; mb = 0; h = c; }
        else { const int cl = c - L0CH; Pb = C0; mb = (cl & 3) * 32; h = cl >> 2; }
        const int ph = posk(h);

        #pragma unroll
        for (int sp = 0; sp < 2; ++sp) {
            // A fragments: W^T rows n, conflict-free rotated float4 loads
            float4 aF[2][2];
            #pragma unroll
            for (int nt = 0; nt < 2; ++nt)
                #pragma unroll
                for (int rh = 0; rh < 2; ++rh) {
                    const int n = wn * 32 + nt * 16 + lq + 8 * rh;
                    aF[nt][rh] = *reinterpret_cast<const float4*>(
                        Wt + n * 32 + ((4 * sp + lr + 4 * n) & 7) * 4);
                }
            #pragma unroll
            for (int bb = 0; bb < 2; ++bb) {
                const int bidx = bp * 2 + bb;
                const float* Pbb = Pb + bidx * (l0 ? UP_SZ : C0_SZ);
                const float* Ubb = Up + bidx * UP_SZ;
                u32 bf[4][4];   // [dt][s01*2 + {b0,b1}]
                #pragma unroll
                for (int dt = 0; dt < 4; ++dt) {
                    const int d = dt * 8 + lq;
                    const float uh = Ubb[d * UPSTR + ph];
                    float4 pv;
                    if (l0)
                        pv = *reinterpret_cast<const float4*>(
                            Pbb + d * UPSTR + sp * 16 + lr * 4);
                    else
                        pv = *reinterpret_cast<const float4*>(
                            Pbb + d * 128 +
                            ((((mb >> 2) + sp * 4 + lr + 4 * d) & 31) << 2));
                    bf[dt][0] = cvt_tf32(uh * pv.x);
                    bf[dt][1] = cvt_tf32(uh * pv.y);
                    bf[dt][2] = cvt_tf32(uh * pv.z);
                    bf[dt][3] = cvt_tf32(uh * pv.w);
                }
                #pragma unroll
                for (int s01 = 0; s01 < 2; ++s01)
                    #pragma unroll
                    for (int dt = 0; dt < 4; ++dt)
                        #pragma unroll
                        for (int nt = 0; nt < 2; ++nt) {
                            u32 a[4];
                            if (s01 == 0) {
                                a[0] = __float_as_uint(aF[nt][0].x);
                                a[1] = __float_as_uint(aF[nt][1].x);
                                a[2] = __float_as_uint(aF[nt][0].y);
                                a[3] = __float_as_uint(aF[nt][1].y);
                            } else {
                                a[0] = __float_as_uint(aF[nt][0].z);
                                a[1] = __float_as_uint(aF[nt][1].z);
                                a[2] = __float_as_uint(aF[nt][0].w);
                                a[3] = __float_as_uint(aF[nt][1].w);
                            }
                            mma8(acc[nt][bb][dt], a, &bf[dt][s01 * 2]);
                        }
            }
        }
    }

    // ---- epilogue 1 ----
    #pragma unroll
    for (int bb = 0; bb < 2; ++bb) {
        const int bidx = bp * 2 + bb;
        const size_t bg = (size_t)blockIdx.x * 4 + bidx;
        #pragma unroll
        for (int nt = 0; nt < 2; ++nt) {
            float srow[2] = {0.f, 0.f};
            #pragma unroll
            for (int dt = 0; dt < 4; ++dt)
                #pragma unroll
                for (int cc = 0; cc < 4; ++cc)
                    srow[cc >> 1] += fmaxf(acc[nt][bb][dt][cc], 0.f);
            #pragma unroll
            for (int o = 1; o < 4; o <<= 1) {
                srow[0] += __shfl_xor_sync(0xffffffffu, srow[0], o);
                srow[1] += __shfl_xor_sync(0xffffffffu, srow[1], o);
            }
            if (lr == 0) {
                const int n = wn * 32 + nt * 16 + lq;
                out[bg * 256 + 128 + n]     = srow[0];
                out[bg * 256 + 128 + n + 8] = srow[1];
            }
        }
    }
}

extern "C" void kernel_launch(void* const* d_in, const int* in_sizes, int n_in,
                              void* d_out, int out_size) {
    const float* x  = (const float*)d_in[0];   // inputs   [4096,32,32]
    const float* w0 = (const float*)d_in[1];   // filter_0 [1,1024,128]
    const float* w1 = (const float*)d_in[2];   // filter_1 [1,4096,128]
    float* out = (float*)d_out;                // [4096, 256]
    (void)in_sizes; (void)n_in; (void)out_size;

    cudaFuncSetAttribute(cin_main, cudaFuncAttributeMaxDynamicSharedMemorySize,
                         SMEM_F * sizeof(float));
    cin_prep<<<NCH, 128>>>(w0, w1);
    cin_main<<<1024, NT, SMEM_F * sizeof(float)>>>(x, out);
}

// round 9
// speedup vs baseline: 1.3147x; 1.3147x over previous
#include <cuda_runtime.h>

// CIN (xDeepFM) fused 2-layer kernel, round 9 — R7 chassis, single-term tf32.
// B=4096, F=32, D=32, layers [128,128].
//
// GEMM view per batch: 32 d-rows x 128 n, K0=1024, K1=4096.
//   z0[d][k=h*32+m]  = u[h][d]*u[m][d]
//   z1[d][k=h*128+m] = u[h][d]*relu(cur0)[m][d]
// Single-term tf32: z rounded rna (cvt.rna.tf32), W pre-rounded rna by a
// prep kernel. acc += z_tf32 * W_tf32 (fp32 accum). Measured-basis rel_err
// ~1.3e-4 (R8) vs 1e-3 threshold.
//
// CTA = 2 batches (M64 x N128), 256 threads, 8 warps of M32 x N32
// (warp = one batch x one n-block), 2 CTAs/SM. A fragments built in
// registers; W chunks (KC=32) reg-prefetched, double-buffered smem,
// one __syncthreads per chunk.

typedef unsigned int u32;

// tf32-pre-rounded W, chunk-contiguous: g_w[c*4096 + kl*128 + n]
__device__ float g_w[160 * 4096];

namespace {
constexpr int NT    = 256;
constexpr int L0CH  = 32;     // layer-0 chunks (K=1024/32)
constexpr int NCH   = 160;    // + layer-1 chunks (K=4096/32)
constexpr int USTR  = 36;     // Ud  [d][h] stride (bank-injective)
constexpr int CSTR  = 132;    // C0  [d][m] stride (bank-injective)
constexpr int WSTR  = 136;    // Wt  [k][n] stride (bank-injective)
constexpr int UD_SZ = 32 * USTR;   // 1152 floats / batch
constexpr int C0_SZ = 32 * CSTR;   // 4224 floats / batch
constexpr int WT_SZ = 32 * WSTR;   // 4352 floats / buffer
constexpr int UD_OFF = 0;
constexpr int C0_OFF = UD_OFF + 2 * UD_SZ;   // 2304
constexpr int WT_OFF = C0_OFF + 2 * C0_SZ;   // 10752
constexpr int SMEM_F = WT_OFF + 2 * WT_SZ;   // 19456 floats = 76 KB
}

__device__ __forceinline__ u32 cvt_tf32(float x) {
    u32 h;
    asm("cvt.rna.tf32.f32 %0, %1;" : "=r"(h) : "f"(x));
    return h;
}

// D(16x8) += A(16x8,tf32,row) * B(8x8,tf32,col), fp32 accum.
__device__ __forceinline__ void mma8(float* d, const u32* a, const u32* b) {
    asm volatile(
        "mma.sync.aligned.m16n8k8.row.col.f32.tf32.tf32.f32 "
        "{%0,%1,%2,%3}, {%4,%5,%6,%7}, {%8,%9}, {%0,%1,%2,%3};"
        : "+f"(d[0]), "+f"(d[1]), "+f"(d[2]), "+f"(d[3])
        : "r"(a[0]), "r"(a[1]), "r"(a[2]), "r"(a[3]), "r"(b[0]), "r"(b[1]));
}

// ---- prep: round W to tf32 once (chunk-contiguous copy) --------------------
__global__ __launch_bounds__(256) void cin_prep(const float* __restrict__ w0,
                                                const float* __restrict__ w1) {
    const int i = blockIdx.x * 256 + threadIdx.x;   // over 160*4096 elements
    const float v = (i < L0CH * 4096) ? w0[i] : w1[i - L0CH * 4096];
    g_w[i] = __uint_as_float(cvt_tf32(v));
}

// ---- main ------------------------------------------------------------------
__global__ __launch_bounds__(NT, 2) void cin_mma(
    const float* __restrict__ x,    // [4096, 32, 32]
    float* __restrict__ out)        // [4096, 256]
{
    extern __shared__ __align__(16) float sm[];
    float* const Ud = sm + UD_OFF;   // [2 batch][d*36 + h]
    float* const C0 = sm + C0_OFF;   // [2 batch][d*132 + m]
    float* const Wt = sm + WT_OFF;   // [2 buf][k*136 + n]  (tf32-rounded)

    const int t    = threadIdx.x;
    const int lane = t & 31;
    const int wid  = t >> 5;
    const int bs   = wid >> 2;     // batch within CTA
    const int wn   = wid & 3;      // N block: n in [32wn, 32wn+32)
    const int lq   = lane >> 2;    // groupID 0..7
    const int lr   = lane & 3;     // threadID_in_group 0..3

    // ---- load 2 batches of inputs transposed into Ud[bs][d][h] ----
    for (int i = t; i < 2048; i += NT) {
        const int ib = i >> 10, h = (i >> 5) & 31, d = i & 31;
        Ud[ib * UD_SZ + d * USTR + h] = x[(size_t)blockIdx.x * 2048 + i];
    }

    float acc[2][4][4];   // [mtile(d-half)][ntile][creg]
    #pragma unroll
    for (int a = 0; a < 2; ++a)
        #pragma unroll
        for (int b = 0; b < 4; ++b)
            #pragma unroll
            for (int r = 0; r < 4; ++r) acc[a][b][r] = 0.f;

    // ---- prefetch W chunk 0 (already tf32-rounded) ----
    float4 wreg[4];
    {
        const float4* src = reinterpret_cast<const float4*>(g_w);
        #pragma unroll
        for (int g = 0; g < 4; ++g) wreg[g] = src[t * 4 + g];
    }

    for (int c = 0; c < NCH; ++c) {
        // ======== layer boundary: epilogue 0 ========
        if (c == L0CH) {
            const size_t bg = (size_t)blockIdx.x * 2 + bs;
            float* const Cb = C0 + bs * C0_SZ;
            #pragma unroll
            for (int nt = 0; nt < 4; ++nt) {
                const int n = wn * 32 + nt * 8 + 2 * lr;
                float s0 = 0.f, s1 = 0.f;
                #pragma unroll
                for (int tt = 0; tt < 2; ++tt) {
                    const float v0 = fmaxf(acc[tt][nt][0], 0.f);
                    const float v1 = fmaxf(acc[tt][nt][1], 0.f);
                    const float v2 = fmaxf(acc[tt][nt][2], 0.f);
                    const float v3 = fmaxf(acc[tt][nt][3], 0.f);
                    s0 += v0 + v2;
                    s1 += v1 + v3;
                    const int d = tt * 16 + lq;
                    Cb[d * CSTR + n]           = v0;
                    Cb[d * CSTR + n + 1]       = v1;
                    Cb[(d + 8) * CSTR + n]     = v2;
                    Cb[(d + 8) * CSTR + n + 1] = v3;
                }
                #pragma unroll
                for (int o = 4; o < 32; o <<= 1) {
                    s0 += __shfl_xor_sync(0xffffffffu, s0, o);
                    s1 += __shfl_xor_sync(0xffffffffu, s1, o);
                }
                if (lq == 0) {
                    out[bg * 256 + n]     = s0;
                    out[bg * 256 + n + 1] = s1;
                }
            }
            #pragma unroll
            for (int a = 0; a < 2; ++a)
                #pragma unroll
                for (int b = 0; b < 4; ++b)
                    #pragma unroll
                    for (int r = 0; r < 4; ++r) acc[a][b][r] = 0.f;
        }

        // ---- stage prefetched W chunk into buffer c&1 ----
        float* const wb = Wt + (c & 1) * WT_SZ;
        {
            float* dst = wb + (t >> 3) * WSTR + (t & 7) * 16;
            #pragma unroll
            for (int g = 0; g < 4; ++g)
                reinterpret_cast<float4*>(dst)[g] = wreg[g];
        }
        __syncthreads();   // publishes Wt (and Ud on c=0, C0 on c=32)

        // ---- prefetch next chunk (in compute shadow) ----
        if (c + 1 < NCH) {
            const float4* src =
                reinterpret_cast<const float4*>(g_w + (size_t)(c + 1) * 4096);
            #pragma unroll
            for (int g = 0; g < 4; ++g) wreg[g] = src[t * 4 + g];
        }

        // ---- per-chunk operand setup ----
        int h, mb, PS, PSZ;
        const float* Pb;
        if (c < L0CH) { h = c; mb = 0; PS = USTR; PSZ = UD_SZ; Pb = Ud; }
        else {
            const int cl = c - L0CH;
            h = cl >> 2; mb = (cl & 3) * 32; PS = CSTR; PSZ = C0_SZ; Pb = C0;
        }
        const float* pp[2][2];
        float um[2][2];
        {
            const float* Pbatch = Pb + bs * PSZ;
            const float* Ub = Ud + bs * UD_SZ;
            #pragma unroll
            for (int tt = 0; tt < 2; ++tt)
                #pragma unroll
                for (int jb = 0; jb < 2; ++jb) {
                    const int d = tt * 16 + lq + 8 * jb;
                    pp[tt][jb] = Pbatch + d * PS + mb + lr;
                    um[tt][jb] = Ub[d * USTR + h];
                }
        }
        const float* wp = wb + lr * WSTR + wn * 32 + lq;

        // ---- 4 k8 steps: build A frags (rna tf32), 8 MMAs per step ----
        #pragma unroll
        for (int s = 0; s < 4; ++s) {
            u32 bf[4][2];
            #pragma unroll
            for (int nt = 0; nt < 4; ++nt) {
                bf[nt][0] = __float_as_uint(wp[(s * 8) * WSTR + nt * 8]);
                bf[nt][1] = __float_as_uint(wp[(s * 8 + 4) * WSTR + nt * 8]);
            }
            u32 ah[2][4];
            #pragma unroll
            for (int tt = 0; tt < 2; ++tt)
                #pragma unroll
                for (int jk = 0; jk < 2; ++jk)
                    #pragma unroll
                    for (int jb = 0; jb < 2; ++jb) {
                        const float pv = pp[tt][jb][s * 8 + 4 * jk];
                        ah[tt][jk * 2 + jb] = cvt_tf32(um[tt][jb] * pv);
                    }
            #pragma unroll
            for (int nt = 0; nt < 4; ++nt)
                #pragma unroll
                for (int tt = 0; tt < 2; ++tt)
                    mma8(acc[tt][nt], ah[tt], bf[nt]);
        }
    }

    // ======== epilogue 1 ========
    {
        const size_t bg = (size_t)blockIdx.x * 2 + bs;
        #pragma unroll
        for (int nt = 0; nt < 4; ++nt) {
            const int n = wn * 32 + nt * 8 + 2 * lr;
            float s0 = 0.f, s1 = 0.f;
            #pragma unroll
            for (int tt = 0; tt < 2; ++tt) {
                s0 += fmaxf(acc[tt][nt][0], 0.f) + fmaxf(acc[tt][nt][2], 0.f);
                s1 += fmaxf(acc[tt][nt][1], 0.f) + fmaxf(acc[tt][nt][3], 0.f);
            }
            #pragma unroll
            for (int o = 4; o < 32; o <<= 1) {
                s0 += __shfl_xor_sync(0xffffffffu, s0, o);
                s1 += __shfl_xor_sync(0xffffffffu, s1, o);
            }
            if (lq == 0) {
                out[bg * 256 + 128 + n]     = s0;
                out[bg * 256 + 128 + n + 1] = s1;
            }
        }
    }
}

extern "C" void kernel_launch(void* const* d_in, const int* in_sizes, int n_in,
                              void* d_out, int out_size) {
    const float* x  = (const float*)d_in[0];   // inputs   [4096,32,32]
    const float* w0 = (const float*)d_in[1];   // filter_0 [1,1024,128]
    const float* w1 = (const float*)d_in[2];   // filter_1 [1,4096,128]
    float* out = (float*)d_out;                // [4096, 256]
    (void)in_sizes; (void)n_in; (void)out_size;

    cudaFuncSetAttribute(cin_mma, cudaFuncAttributeMaxDynamicSharedMemorySize,
                         SMEM_F * sizeof(float));
    cin_prep<<<(NCH * 4096) / 256, 256>>>(w0, w1);
    cin_mma<<<2048, NT, SMEM_F * sizeof(float)>>>(x, out);
}

// round 11
// speedup vs baseline: 3.4439x; 2.6196x over previous
#include <cuda_runtime.h>

// CIN (xDeepFM) fused 2-layer kernel, round 10 — register P-frags + direct
// fragment-ordered W LDG (no W smem, no mainloop barriers).
// B=4096, F=32, D=32, layers [128,128].
//
// GEMM per batch: 32 d-rows x 128 n; K0=1024, K1=4096.
//   z0[d][k=h*32+m]  = u[h][d]*u[m][d]
//   z1[d][k=h*128+m] = u[h][d]*relu(cur0)[m][d]
// Single-term tf32 (z via cvt.rna, W pre-rounded): measured rel_err ~1.3e-4.
//
// Iteration: m-block outer, h inner => the m-side fragment (u[m][d] or
// c0[m][d]) lives in 32 registers for 32 consecutive chunks. W fragments are
// pre-arranged by cin_prep in exact per-(chunk, n-half, s, nt-pair) order so
// the mainloop reads them with 16 coalesced LDG.128 per chunk per thread.
// CTA = 2 batches x 2 n-halves = 4 warps (128 thr), warp tile M32 x N64,
// 3 CTAs/SM. Only one __syncthreads (layer boundary).

typedef unsigned int u32;

// fragment-ordered, tf32-rounded W: [cc][wn][s*4+ntp][lane][comp]
__device__ __align__(16) float g_w[160 * 4096];

namespace {
constexpr int NT    = 128;
constexpr int USTR  = 36;             // Ud [d][h] stride (4lq+lr injective)
constexpr int CSTR  = 132;            // C0 [d][m] stride (4lq+lr injective)
constexpr int UD_SZ = 32 * USTR;      // 1152 floats / batch
constexpr int C0_SZ = 32 * CSTR;      // 4224 floats / batch
constexpr int C0_OFF = 2 * UD_SZ;     // 2304
constexpr int SMEM_F = C0_OFF + 2 * C0_SZ;   // 10752 floats = 42 KB
}

__device__ __forceinline__ u32 cvt_tf32(float x) {
    u32 h;
    asm("cvt.rna.tf32.f32 %0, %1;" : "=r"(h) : "f"(x));
    return h;
}

// D(16x8) += A(16x8,tf32,row) * B(8x8,tf32,col), fp32 accum.
__device__ __forceinline__ void mma8(float* d, const u32* a, const u32* b) {
    asm volatile(
        "mma.sync.aligned.m16n8k8.row.col.f32.tf32.tf32.f32 "
        "{%0,%1,%2,%3}, {%4,%5,%6,%7}, {%8,%9}, {%0,%1,%2,%3};"
        : "+f"(d[0]), "+f"(d[1]), "+f"(d[2]), "+f"(d[3])
        : "r"(a[0]), "r"(a[1]), "r"(a[2]), "r"(a[3]), "r"(b[0]), "r"(b[1]));
}

// ---- prep: W -> fragment-ordered tf32 layout --------------------------------
// element i: cc = i>>12; within 4096: wn(1b) | s(2b) ntp(2b) | lane(5b) | comp(2b)
// value = W[k = basek(cc) + s*8 + (lane&3) + 4*(comp&1)]
//          [n = wn*64 + (2*ntp + (comp>>1))*8 + (lane>>2)]
__global__ __launch_bounds__(256) void cin_prep(const float* __restrict__ w0,
                                                const float* __restrict__ w1) {
    const int i    = blockIdx.x * 256 + threadIdx.x;   // 0 .. 160*4096-1
    const int cc   = i >> 12;
    const int r    = i & 4095;
    const int wn   = r >> 11;
    const int r2   = r & 2047;
    const int s    = r2 >> 9;
    const int ntp  = (r2 >> 7) & 3;
    const int lane = (r2 >> 2) & 31;
    const int comp = r2 & 3;
    const int kl   = s * 8 + (lane & 3) + 4 * (comp & 1);
    const int n    = wn * 64 + (2 * ntp + (comp >> 1)) * 8 + (lane >> 2);
    float v;
    if (cc < 32) {
        v = w0[(cc * 32 + kl) * 128 + n];
    } else {
        const int cl = cc - 32, mbb = cl >> 5, h = cl & 31;
        v = w1[(h * 128 + mbb * 32 + kl) * 128 + n];
    }
    g_w[i] = __uint_as_float(cvt_tf32(v));
}

// ---- one 32-chunk block (fixed m-side fragment pv) --------------------------
__device__ __forceinline__ void run_block(
    float acc[2][8][4],
    const float pv[2][4][2][2],    // [tt][s][jk][jb] = m-side factor
    const float* __restrict__ Ub,  // this batch's Ud
    int ccb, int wn, int lane, int lq, int lr)
{
    for (int h = 0; h < 32; ++h) {
        const int cc = ccb + h;
        const float4* wg = reinterpret_cast<const float4*>(g_w) +
                           ((size_t)cc * 2 + wn) * 512 + lane;
        if (cc + 1 < 160) {   // warm L1 for next chunk's fragments
            const char* nx = reinterpret_cast<const char*>(
                reinterpret_cast<const float4*>(g_w) +
                ((size_t)(cc + 1) * 2 + wn) * 512);
            asm volatile("prefetch.global.L1 [%0];" :: "l"(nx + lane * 128));
            asm volatile("prefetch.global.L1 [%0];" :: "l"(nx + 4096 + lane * 128));
        }
        float um[2][2];
        #pragma unroll
        for (int tt = 0; tt < 2; ++tt)
            #pragma unroll
            for (int jb = 0; jb < 2; ++jb)
                um[tt][jb] = Ub[(tt * 16 + lq + 8 * jb) * USTR + h];

        #pragma unroll
        for (int s = 0; s < 4; ++s) {
            u32 bf[8][2];
            #pragma unroll
            for (int ntp = 0; ntp < 4; ++ntp) {
                const float4 wv = __ldg(&wg[(s * 4 + ntp) * 32]);
                bf[2 * ntp][0]     = __float_as_uint(wv.x);
                bf[2 * ntp][1]     = __float_as_uint(wv.y);
                bf[2 * ntp + 1][0] = __float_as_uint(wv.z);
                bf[2 * ntp + 1][1] = __float_as_uint(wv.w);
            }
            u32 ah[2][4];
            #pragma unroll
            for (int tt = 0; tt < 2; ++tt)
                #pragma unroll
                for (int jk = 0; jk < 2; ++jk)
                    #pragma unroll
                    for (int jb = 0; jb < 2; ++jb)
                        ah[tt][jk * 2 + jb] =
                            cvt_tf32(um[tt][jb] * pv[tt][s][jk][jb]);
            #pragma unroll
            for (int nt = 0; nt < 8; ++nt)
                #pragma unroll
                for (int tt = 0; tt < 2; ++tt)
                    mma8(acc[tt][nt], ah[tt], bf[nt]);
        }
    }
}

// ---- main -------------------------------------------------------------------
__global__ __launch_bounds__(NT, 3) void cin_mma(
    const float* __restrict__ x,    // [4096, 32, 32]
    float* __restrict__ out)        // [4096, 256]
{
    extern __shared__ __align__(16) float sm[];
    float* const Ud = sm;            // [2 batch][d*36 + h]
    float* const C0 = sm + C0_OFF;   // [2 batch][d*132 + m]

    const int t    = threadIdx.x;
    const int lane = t & 31;
    const int wid  = t >> 5;
    const int bs   = wid >> 1;       // batch within CTA
    const int wn   = wid & 1;        // n-half: n in [64wn, 64wn+64)
    const int lq   = lane >> 2;
    const int lr   = lane & 3;

    // stage inputs transposed: x[b][h][d] -> Ud[b][d][h]
    for (int i = t; i < 2048; i += NT) {
        const int ib = i >> 10, h = (i >> 5) & 31, d = i & 31;
        Ud[ib * UD_SZ + d * USTR + h] = x[(size_t)blockIdx.x * 2048 + i];
    }
    __syncthreads();

    const float* const Ub = Ud + bs * UD_SZ;
    float* const Cb = C0 + bs * C0_SZ;
    const size_t bg = (size_t)blockIdx.x * 2 + bs;

    float acc[2][8][4];
    #pragma unroll
    for (int a = 0; a < 2; ++a)
        #pragma unroll
        for (int b = 0; b < 8; ++b)
            #pragma unroll
            for (int r = 0; r < 4; ++r) acc[a][b][r] = 0.f;

    // ================= layer 0: pv = u[m][d], one block of 32 chunks ========
    {
        float pv[2][4][2][2];
        #pragma unroll
        for (int tt = 0; tt < 2; ++tt)
            #pragma unroll
            for (int s = 0; s < 4; ++s)
                #pragma unroll
                for (int jk = 0; jk < 2; ++jk)
                    #pragma unroll
                    for (int jb = 0; jb < 2; ++jb)
                        pv[tt][s][jk][jb] =
                            Ub[(tt * 16 + lq + 8 * jb) * USTR +
                               s * 8 + 4 * jk + lr];
        run_block(acc, pv, Ub, 0, wn, lane, lq, lr);
    }

    // ---- epilogue 0: relu -> C0 + d-sum -> out[bg, 0..128) ----
    #pragma unroll
    for (int nt = 0; nt < 8; ++nt) {
        const int n = wn * 64 + nt * 8 + 2 * lr;
        float s0 = 0.f, s1 = 0.f;
        #pragma unroll
        for (int tt = 0; tt < 2; ++tt) {
            const float v0 = fmaxf(acc[tt][nt][0], 0.f);
            const float v1 = fmaxf(acc[tt][nt][1], 0.f);
            const float v2 = fmaxf(acc[tt][nt][2], 0.f);
            const float v3 = fmaxf(acc[tt][nt][3], 0.f);
            s0 += v0 + v2; s1 += v1 + v3;
            const int d = tt * 16 + lq;
            Cb[d * CSTR + n]           = v0;
            Cb[d * CSTR + n + 1]       = v1;
            Cb[(d + 8) * CSTR + n]     = v2;
            Cb[(d + 8) * CSTR + n + 1] = v3;
        }
        #pragma unroll
        for (int o = 4; o < 32; o <<= 1) {
            s0 += __shfl_xor_sync(0xffffffffu, s0, o);
            s1 += __shfl_xor_sync(0xffffffffu, s1, o);
        }
        if (lq == 0) {
            out[bg * 256 + n]     = s0;
            out[bg * 256 + n + 1] = s1;
        }
    }
    #pragma unroll
    for (int a = 0; a < 2; ++a)
        #pragma unroll
        for (int b = 0; b < 8; ++b)
            #pragma unroll
            for (int r = 0; r < 4; ++r) acc[a][b][r] = 0.f;
    __syncthreads();   // C0 visible to both n-half warps

    // ================= layer 1: 4 m-blocks, pv = c0[m][d] ===================
    for (int mbb = 0; mbb < 4; ++mbb) {
        float pv[2][4][2][2];
        #pragma unroll
        for (int tt = 0; tt < 2; ++tt)
            #pragma unroll
            for (int s = 0; s < 4; ++s)
                #pragma unroll
                for (int jk = 0; jk < 2; ++jk)
                    #pragma unroll
                    for (int jb = 0; jb < 2; ++jb)
                        pv[tt][s][jk][jb] =
                            Cb[(tt * 16 + lq + 8 * jb) * CSTR +
                               mbb * 32 + s * 8 + 4 * jk + lr];
        run_block(acc, pv, Ub, 32 + mbb * 32, wn, lane, lq, lr);
    }

    // ---- epilogue 1: relu + d-sum -> out[bg, 128..256) ----
    #pragma unroll
    for (int nt = 0; nt < 8; ++nt) {
        const int n = wn * 64 + nt * 8 + 2 * lr;
        float s0 = 0.f, s1 = 0.f;
        #pragma unroll
        for (int tt = 0; tt < 2; ++tt) {
            s0 += fmaxf(acc[tt][nt][0], 0.f) + fmaxf(acc[tt][nt][2], 0.f);
            s1 += fmaxf(acc[tt][nt][1], 0.f) + fmaxf(acc[tt][nt][3], 0.f);
        }
        #pragma unroll
        for (int o = 4; o < 32; o <<= 1) {
            s0 += __shfl_xor_sync(0xffffffffu, s0, o);
            s1 += __shfl_xor_sync(0xffffffffu, s1, o);
        }
        if (lq == 0) {
            out[bg * 256 + 128 + n]     = s0;
            out[bg * 256 + 128 + n + 1] = s1;
        }
    }
}

extern "C" void kernel_launch(void* const* d_in, const int* in_sizes, int n_in,
                              void* d_out, int out_size) {
    const float* x  = (const float*)d_in[0];   // inputs   [4096,32,32]
    const float* w0 = (const float*)d_in[1];   // filter_0 [1,1024,128]
    const float* w1 = (const float*)d_in[2];   // filter_1 [1,4096,128]
    float* out = (float*)d_out;                // [4096, 256]
    (void)in_sizes; (void)n_in; (void)out_size;

    cudaFuncSetAttribute(cin_mma, cudaFuncAttributeMaxDynamicSharedMemorySize,
                         SMEM_F * sizeof(float));
    cin_prep<<<(160 * 4096) / 256, 256>>>(w0, w1);
    cin_mma<<<2048, NT, SMEM_F * sizeof(float)>>>(x, out);
}

// round 14
// speedup vs baseline: 6.4620x; 1.8764x over previous
#include <cuda_runtime.h>

// CIN (xDeepFM) fused 2-layer kernel, round 14 — fp16 m16n8k16 single-term,
// with the R12/13 W-fragment stride bug fixed ((cc*2+wn)*256 / (S*4+j4)*32).
// B=4096, F=32, D=32, layers [128,128].
//
// GEMM per batch: 32 d-rows x 128 n; K0=1024, K1=4096.
//   z0[d][k=h*32+m]  = u[h][d]*u[m][d]
//   z1[d][k=h*128+m] = u[h][d]*relu(cur0)[m][d]
// fp16 operands (10 mantissa bits == tf32), fp32 accumulate.
//
// Chassis = round 10/11: m-block outer / h inner so the m-side fragment lives
// in registers for 32 consecutive chunks; W pre-rounded+packed fp16x2 in exact
// fragment order (cin_prep) and read with coalesced LDG.128 (no W smem, no
// mainloop barriers). CTA = 2 batches x 2 n-halves = 4 warps, warp tile
// M32 x N64, 3 CTAs/SM. MMA = m16n8k16 (half the instructions of tf32 k8).

typedef unsigned int u32;

// fragment-ordered fp16x2 W: per chunk cc (2048 u32), per wn (1024 u32):
// u32 index r = wn*1024 + S*512 + j4*128 + lane*4 + c,
// value = {hi = W[k0+1][n], lo = W[k0][n]} fp16,
//   k0 = chunkbase + S*16 + 2*(lane&3) + 8*(c&1),
//   n  = wn*64 + (2*j4 + (c>>1))*8 + (lane>>2).
__device__ __align__(16) u32 g_w[160 * 2048];

namespace {
constexpr int NT    = 128;
constexpr int USTR  = 36;             // Ud [d][h] stride
constexpr int CSTR  = 132;            // C0 [d][m] stride
constexpr int UD_SZ = 32 * USTR;      // 1152 floats / batch
constexpr int C0_SZ = 32 * CSTR;      // 4224 floats / batch
constexpr int C0_OFF = 2 * UD_SZ;     // 2304
constexpr int SMEM_F = C0_OFF + 2 * C0_SZ;   // 10752 floats = 42 KB
}

__device__ __forceinline__ u32 packh2(float lo, float hi) {
    u32 r;
    asm("cvt.rn.f16x2.f32 %0, %1, %2;" : "=r"(r) : "f"(hi), "f"(lo));
    return r;
}

// D(16x8,f32) += A(16x16,f16,row) * B(16x8,f16,col)
__device__ __forceinline__ void mma16(float* d, const u32* a, const u32* b) {
    asm volatile(
        "mma.sync.aligned.m16n8k16.row.col.f32.f16.f16.f32 "
        "{%0,%1,%2,%3}, {%4,%5,%6,%7}, {%8,%9}, {%0,%1,%2,%3};"
        : "+f"(d[0]), "+f"(d[1]), "+f"(d[2]), "+f"(d[3])
        : "r"(a[0]), "r"(a[1]), "r"(a[2]), "r"(a[3]), "r"(b[0]), "r"(b[1]));
}

// ---- prep: W -> fragment-ordered fp16x2 -------------------------------------
__global__ __launch_bounds__(256) void cin_prep(const float* __restrict__ w0,
                                                const float* __restrict__ w1) {
    const int i    = blockIdx.x * 256 + threadIdx.x;   // 0 .. 160*2048-1
    const int cc   = i >> 11;
    const int r    = i & 2047;
    const int wn   = r >> 10;
    const int S    = (r >> 9) & 1;
    const int j4   = (r >> 7) & 3;
    const int lane = (r >> 2) & 31;
    const int c    = r & 3;
    const int nt   = 2 * j4 + (c >> 1);
    const int k0   = S * 16 + 2 * (lane & 3) + 8 * (c & 1);
    const int n    = wn * 64 + nt * 8 + (lane >> 2);
    float va, vb;
    if (cc < 32) {
        va = w0[(cc * 32 + k0) * 128 + n];
        vb = w0[(cc * 32 + k0 + 1) * 128 + n];
    } else {
        const int cl = cc - 32, mbb = cl >> 5, h = cl & 31;
        va = w1[(h * 128 + mbb * 32 + k0) * 128 + n];
        vb = w1[(h * 128 + mbb * 32 + k0 + 1) * 128 + n];
    }
    g_w[i] = packh2(va, vb);
}

// ---- one 32-chunk block (fixed m-side fragment pv) --------------------------
// pv[tt][jb][S][kh][c] = P[mbase + S*16 + 2lr + 8kh + c][d = tt*16+lq+8jb]
__device__ __forceinline__ void run_block(
    float acc[2][8][4],
    const float pv[2][2][2][2][2],
    const float* __restrict__ Ub,
    int ccb, int wn, int lane, int lq, int lr)
{
    for (int h = 0; h < 32; ++h) {
        const int cc = ccb + h;
        // per-(chunk, wn) region = 256 float4; per-(S,j4) block = 32 float4
        const float4* wg = reinterpret_cast<const float4*>(g_w) +
                           ((size_t)cc * 2 + wn) * 256 + lane;
        if (cc + 1 < 160) {   // warm L1 for next chunk's fragments (4KB region)
            const char* nx = reinterpret_cast<const char*>(
                reinterpret_cast<const float4*>(g_w) +
                ((size_t)(cc + 1) * 2 + wn) * 256);
            asm volatile("prefetch.global.L1 [%0];" :: "l"(nx + lane * 128));
        }
        float um[2][2];
        #pragma unroll
        for (int tt = 0; tt < 2; ++tt)
            #pragma unroll
            for (int jb = 0; jb < 2; ++jb)
                um[tt][jb] = Ub[(tt * 16 + lq + 8 * jb) * USTR + h];

        #pragma unroll
        for (int S = 0; S < 2; ++S) {
            u32 bf[8][2];
            #pragma unroll
            for (int j4 = 0; j4 < 4; ++j4) {
                const float4 wv = __ldg(&wg[(S * 4 + j4) * 32]);
                bf[2 * j4][0]     = __float_as_uint(wv.x);
                bf[2 * j4][1]     = __float_as_uint(wv.y);
                bf[2 * j4 + 1][0] = __float_as_uint(wv.z);
                bf[2 * j4 + 1][1] = __float_as_uint(wv.w);
            }
            u32 ah[2][4];
            #pragma unroll
            for (int tt = 0; tt < 2; ++tt)
                #pragma unroll
                for (int kh = 0; kh < 2; ++kh)
                    #pragma unroll
                    for (int jb = 0; jb < 2; ++jb)
                        ah[tt][kh * 2 + jb] =
                            packh2(um[tt][jb] * pv[tt][jb][S][kh][0],
                                   um[tt][jb] * pv[tt][jb][S][kh][1]);
            #pragma unroll
            for (int nt = 0; nt < 8; ++nt)
                #pragma unroll
                for (int tt = 0; tt < 2; ++tt)
                    mma16(acc[tt][nt], ah[tt], bf[nt]);
        }
    }
}

// ---- main -------------------------------------------------------------------
__global__ __launch_bounds__(NT, 3) void cin_mma(
    const float* __restrict__ x,    // [4096, 32, 32]
    float* __restrict__ out)        // [4096, 256]
{
    extern __shared__ __align__(16) float sm[];
    float* const Ud = sm;            // [2 batch][d*36 + h]
    float* const C0 = sm + C0_OFF;   // [2 batch][d*132 + m]

    const int t    = threadIdx.x;
    const int lane = t & 31;
    const int wid  = t >> 5;
    const int bs   = wid >> 1;       // batch within CTA
    const int wn   = wid & 1;        // n-half: n in [64wn, 64wn+64)
    const int lq   = lane >> 2;
    const int lr   = lane & 3;

    // stage inputs transposed: x[b][h][d] -> Ud[b][d][h]
    for (int i = t; i < 2048; i += NT) {
        const int ib = i >> 10, h = (i >> 5) & 31, d = i & 31;
        Ud[ib * UD_SZ + d * USTR + h] = x[(size_t)blockIdx.x * 2048 + i];
    }
    __syncthreads();

    const float* const Ub = Ud + bs * UD_SZ;
    float* const Cb = C0 + bs * C0_SZ;
    const size_t bg = (size_t)blockIdx.x * 2 + bs;

    float acc[2][8][4];
    #pragma unroll
    for (int a = 0; a < 2; ++a)
        #pragma unroll
        for (int b = 0; b < 8; ++b)
            #pragma unroll
            for (int r = 0; r < 4; ++r) acc[a][b][r] = 0.f;

    // ================= layer 0: pv = u[m][d] ================================
    {
        float pv[2][2][2][2][2];
        #pragma unroll
        for (int tt = 0; tt < 2; ++tt)
            #pragma unroll
            for (int jb = 0; jb < 2; ++jb)
                #pragma unroll
                for (int S = 0; S < 2; ++S)
                    #pragma unroll
                    for (int kh = 0; kh < 2; ++kh)
                        #pragma unroll
                        for (int c = 0; c < 2; ++c)
                            pv[tt][jb][S][kh][c] =
                                Ub[(tt * 16 + lq + 8 * jb) * USTR +
                                   S * 16 + 2 * lr + 8 * kh + c];
        run_block(acc, pv, Ub, 0, wn, lane, lq, lr);
    }

    // ---- epilogue 0: relu -> C0 + d-sum -> out[bg, 0..128) ----
    #pragma unroll
    for (int nt = 0; nt < 8; ++nt) {
        const int n = wn * 64 + nt * 8 + 2 * lr;
        float s0 = 0.f, s1 = 0.f;
        #pragma unroll
        for (int tt = 0; tt < 2; ++tt) {
            const float v0 = fmaxf(acc[tt][nt][0], 0.f);
            const float v1 = fmaxf(acc[tt][nt][1], 0.f);
            const float v2 = fmaxf(acc[tt][nt][2], 0.f);
            const float v3 = fmaxf(acc[tt][nt][3], 0.f);
            s0 += v0 + v2; s1 += v1 + v3;
            const int d = tt * 16 + lq;
            Cb[d * CSTR + n]           = v0;
            Cb[d * CSTR + n + 1]       = v1;
            Cb[(d + 8) * CSTR + n]     = v2;
            Cb[(d + 8) * CSTR + n + 1] = v3;
        }
        #pragma unroll
        for (int o = 4; o < 32; o <<= 1) {
            s0 += __shfl_xor_sync(0xffffffffu, s0, o);
            s1 += __shfl_xor_sync(0xffffffffu, s1, o);
        }
        if (lq == 0) {
            out[bg * 256 + n]     = s0;
            out[bg * 256 + n + 1] = s1;
        }
    }
    #pragma unroll
    for (int a = 0; a < 2; ++a)
        #pragma unroll
        for (int b = 0; b < 8; ++b)
            #pragma unroll
            for (int r = 0; r < 4; ++r) acc[a][b][r] = 0.f;
    __syncthreads();   // C0 visible to both n-half warps

    // ================= layer 1: 4 m-blocks, pv = c0[m][d] ===================
    for (int mbb = 0; mbb < 4; ++mbb) {
        float pv[2][2][2][2][2];
        #pragma unroll
        for (int tt = 0; tt < 2; ++tt)
            #pragma unroll
            for (int jb = 0; jb < 2; ++jb)
                #pragma unroll
                for (int S = 0; S < 2; ++S)
                    #pragma unroll
                    for (int kh = 0; kh < 2; ++kh)
                        #pragma unroll
                        for (int c = 0; c < 2; ++c)
                            pv[tt][jb][S][kh][c] =
                                Cb[(tt * 16 + lq + 8 * jb) * CSTR +
                                   mbb * 32 + S * 16 + 2 * lr + 8 * kh + c];
        run_block(acc, pv, Ub, 32 + mbb * 32, wn, lane, lq, lr);
    }

    // ---- epilogue 1: relu + d-sum -> out[bg, 128..256) ----
    #pragma unroll
    for (int nt = 0; nt < 8; ++nt) {
        const int n = wn * 64 + nt * 8 + 2 * lr;
        float s0 = 0.f, s1 = 0.f;
        #pragma unroll
        for (int tt = 0; tt < 2; ++tt) {
            s0 += fmaxf(acc[tt][nt][0], 0.f) + fmaxf(acc[tt][nt][2], 0.f);
            s1 += fmaxf(acc[tt][nt][1], 0.f) + fmaxf(acc[tt][nt][3], 0.f);
        }
        #pragma unroll
        for (int o = 4; o < 32; o <<= 1) {
            s0 += __shfl_xor_sync(0xffffffffu, s0, o);
            s1 += __shfl_xor_sync(0xffffffffu, s1, o);
        }
        if (lq == 0) {
            out[bg * 256 + 128 + n]     = s0;
            out[bg * 256 + 128 + n + 1] = s1;
        }
    }
}

extern "C" void kernel_launch(void* const* d_in, const int* in_sizes, int n_in,
                              void* d_out, int out_size) {
    const float* x  = (const float*)d_in[0];   // inputs   [4096,32,32]
    const float* w0 = (const float*)d_in[1];   // filter_0 [1,1024,128]
    const float* w1 = (const float*)d_in[2];   // filter_1 [1,4096,128]
    float* out = (float*)d_out;                // [4096, 256]
    (void)in_sizes; (void)n_in; (void)out_size;

    cudaFuncSetAttribute(cin_mma, cudaFuncAttributeMaxDynamicSharedMemorySize,
                         SMEM_F * sizeof(float));
    cin_prep<<<(160 * 2048) / 256, 256>>>(w0, w1);
    cin_mma<<<2048, NT, SMEM_F * sizeof(float)>>>(x, out);
}

// round 15
// speedup vs baseline: 7.3881x; 1.1433x over previous
#include <cuda_runtime.h>
#include <cuda_fp16.h>

// CIN (xDeepFM) fused 2-layer kernel, round 15 — fp16 m16n8k16, HMUL2 A-build.
// B=4096, F=32, D=32, layers [128,128].
//
// GEMM per batch: 32 d-rows x 128 n; K0=1024, K1=4096.
//   z0[d][k=h*32+m]  = u[h][d]*u[m][d]
//   z1[d][k=h*128+m] = u[h][d]*relu(cur0)[m][d]
// fp16 operands, fp32 accumulate. m-side factors pre-packed as half2 pairs
// (u -> Uh2 at staging; relu(c0) -> Ch2 at epilogue 0); h-side factor
// broadcast to half2 once per h; A fragments = one HMUL2 each (lat 4).
//
// W pre-rounded+packed fp16x2 in exact fragment order (cin_prep), read with
// coalesced LDG.128 (no W smem, no mainloop barriers). CTA = 2 batches x
// 2 n-halves = 4 warps, warp tile M32 x N64, 3 CTAs/SM.

typedef unsigned int u32;

// fragment-ordered fp16x2 W: per chunk cc (2048 u32), per wn (1024 u32):
// u32 index r = wn*1024 + S*512 + j4*128 + lane*4 + c,
// value = {hi = W[k0+1][n], lo = W[k0][n]} fp16,
//   k0 = chunkbase + S*16 + 2*(lane&3) + 8*(c&1),
//   n  = wn*64 + (2*j4 + (c>>1))*8 + (lane>>2).
__device__ __align__(16) u32 g_w[160 * 2048];

namespace {
constexpr int NT     = 128;
constexpr int USTR   = 36;              // Ud [d][h] fp32 stride
constexpr int UHSTR  = 20;              // Uh2 [d][m2] half2 stride (bank 4lq+lr)
constexpr int CHSTR  = 68;              // Ch2 [d][n2] half2 stride (bank 4lq+lr)
constexpr int UD_SZ  = 32 * USTR;       // 1152 floats / batch
constexpr int UH_SZ  = 32 * UHSTR;      // 640 half2 / batch
constexpr int CH_SZ  = 32 * CHSTR;      // 2176 half2 / batch
constexpr int UD_BYTES = 2 * UD_SZ * 4;           // 9216
constexpr int UH_BYTES = 2 * UH_SZ * 4;           // 5120
constexpr int CH_BYTES = 2 * CH_SZ * 4;           // 17408
constexpr int SMEM_BYTES = UD_BYTES + UH_BYTES + CH_BYTES;   // 31744
}

__device__ __forceinline__ u32 packh2(float lo, float hi) {
    u32 r;
    asm("cvt.rn.f16x2.f32 %0, %1, %2;" : "=r"(r) : "f"(hi), "f"(lo));
    return r;
}
__device__ __forceinline__ u32 h2u(__half2 v) {
    return *reinterpret_cast<u32*>(&v);
}

// D(16x8,f32) += A(16x16,f16,row) * B(16x8,f16,col)
__device__ __forceinline__ void mma16(float* d, const u32* a, const u32* b) {
    asm volatile(
        "mma.sync.aligned.m16n8k16.row.col.f32.f16.f16.f32 "
        "{%0,%1,%2,%3}, {%4,%5,%6,%7}, {%8,%9}, {%0,%1,%2,%3};"
        : "+f"(d[0]), "+f"(d[1]), "+f"(d[2]), "+f"(d[3])
        : "r"(a[0]), "r"(a[1]), "r"(a[2]), "r"(a[3]), "r"(b[0]), "r"(b[1]));
}

// ---- prep: W -> fragment-ordered fp16x2 (unchanged from round 14) ----------
__global__ __launch_bounds__(256) void cin_prep(const float* __restrict__ w0,
                                                const float* __restrict__ w1) {
    const int i    = blockIdx.x * 256 + threadIdx.x;   // 0 .. 160*2048-1
    const int cc   = i >> 11;
    const int r    = i & 2047;
    const int wn   = r >> 10;
    const int S    = (r >> 9) & 1;
    const int j4   = (r >> 7) & 3;
    const int lane = (r >> 2) & 31;
    const int c    = r & 3;
    const int nt   = 2 * j4 + (c >> 1);
    const int k0   = S * 16 + 2 * (lane & 3) + 8 * (c & 1);
    const int n    = wn * 64 + nt * 8 + (lane >> 2);
    float va, vb;
    if (cc < 32) {
        va = w0[(cc * 32 + k0) * 128 + n];
        vb = w0[(cc * 32 + k0 + 1) * 128 + n];
    } else {
        const int cl = cc - 32, mbb = cl >> 5, h = cl & 31;
        va = w1[(h * 128 + mbb * 32 + k0) * 128 + n];
        vb = w1[(h * 128 + mbb * 32 + k0 + 1) * 128 + n];
    }
    g_w[i] = packh2(va, vb);
}

// ---- one 32-chunk block (fixed m-side half2 fragments pv) -------------------
// pv[tt][jb][S][kh] = half2{ P[m0][d], P[m0+1][d] },
//   m0 = mbase + S*16 + 2lr + 8kh,  d = tt*16 + lq + 8jb.
__device__ __forceinline__ void run_block(
    float acc[2][8][4],
    const __half2 pv[2][2][2][2],
    const float* __restrict__ Ub,     // fp32 Ud of this batch (h-side factor)
    int ccb, int wn, int lane, int lq, int lr)
{
    for (int h = 0; h < 32; ++h) {
        const int cc = ccb + h;
        const float4* wg = reinterpret_cast<const float4*>(g_w) +
                           ((size_t)cc * 2 + wn) * 256 + lane;
        if (cc + 1 < 160) {   // warm L1 for next chunk's fragments (4KB region)
            const char* nx = reinterpret_cast<const char*>(
                reinterpret_cast<const float4*>(g_w) +
                ((size_t)(cc + 1) * 2 + wn) * 256);
            asm volatile("prefetch.global.L1 [%0];" :: "l"(nx + lane * 128));
        }
        __half2 um2[2][2];
        #pragma unroll
        for (int tt = 0; tt < 2; ++tt)
            #pragma unroll
            for (int jb = 0; jb < 2; ++jb)
                um2[tt][jb] = __float2half2_rn(
                    Ub[(tt * 16 + lq + 8 * jb) * USTR + h]);

        #pragma unroll
        for (int S = 0; S < 2; ++S) {
            u32 bf[8][2];
            #pragma unroll
            for (int j4 = 0; j4 < 4; ++j4) {
                const float4 wv = __ldg(&wg[(S * 4 + j4) * 32]);
                bf[2 * j4][0]     = __float_as_uint(wv.x);
                bf[2 * j4][1]     = __float_as_uint(wv.y);
                bf[2 * j4 + 1][0] = __float_as_uint(wv.z);
                bf[2 * j4 + 1][1] = __float_as_uint(wv.w);
            }
            u32 ah[2][4];
            #pragma unroll
            for (int tt = 0; tt < 2; ++tt)
                #pragma unroll
                for (int kh = 0; kh < 2; ++kh)
                    #pragma unroll
                    for (int jb = 0; jb < 2; ++jb)
                        ah[tt][kh * 2 + jb] =
                            h2u(__hmul2(um2[tt][jb], pv[tt][jb][S][kh]));
            #pragma unroll
            for (int nt = 0; nt < 8; ++nt)
                #pragma unroll
                for (int tt = 0; tt < 2; ++tt)
                    mma16(acc[tt][nt], ah[tt], bf[nt]);
        }
    }
}

// ---- main -------------------------------------------------------------------
__global__ __launch_bounds__(NT, 3) void cin_mma(
    const float* __restrict__ x,    // [4096, 32, 32]
    float* __restrict__ out)        // [4096, 256]
{
    extern __shared__ __align__(16) char sm[];
    float*   const Ud = reinterpret_cast<float*>(sm);               // [2][d*36+h]
    __half2* const Uh = reinterpret_cast<__half2*>(sm + UD_BYTES);  // [2][d*20+m2]
    __half2* const Ch = reinterpret_cast<__half2*>(sm + UD_BYTES + UH_BYTES);

    const int t    = threadIdx.x;
    const int lane = t & 31;
    const int wid  = t >> 5;
    const int bs   = wid >> 1;       // batch within CTA
    const int wn   = wid & 1;        // n-half: n in [64wn, 64wn+64)
    const int lq   = lane >> 2;
    const int lr   = lane & 3;

    // stage inputs transposed: x[b][h][d] -> Ud[b][d][h]
    for (int i = t; i < 2048; i += NT) {
        const int ib = i >> 10, h = (i >> 5) & 31, d = i & 31;
        Ud[ib * UD_SZ + d * USTR + h] = x[(size_t)blockIdx.x * 2048 + i];
    }
    __syncthreads();
    // pack u into half2 pairs over m: Uh[b][d][m2] = {u[2m2][d], u[2m2+1][d]}
    for (int e = t; e < 1024; e += NT) {
        const int ib = e >> 9, r = e & 511, d = r >> 4, m2 = r & 15;
        const float* src = Ud + ib * UD_SZ + d * USTR;  // wrong index dir? see below
        // u[m][d] is Ud[b][d*USTR + m]? No: Ud[b][d][h] holds x[b][h][d] at [d][h].
        // m-side factor P[m][d] = x[b][m][d] = Ud[b][d*USTR + m]. Correct:
        Uh[ib * UH_SZ + d * UHSTR + m2] =
            __floats2half2_rn(src[2 * m2], src[2 * m2 + 1]);
    }
    __syncthreads();

    const float* const Ub = Ud + bs * UD_SZ;
    const __half2* const Uhb = Uh + bs * UH_SZ;
    __half2* const Chb = Ch + bs * CH_SZ;
    const size_t bg = (size_t)blockIdx.x * 2 + bs;

    float acc[2][8][4];
    #pragma unroll
    for (int a = 0; a < 2; ++a)
        #pragma unroll
        for (int b = 0; b < 8; ++b)
            #pragma unroll
            for (int r = 0; r < 4; ++r) acc[a][b][r] = 0.f;

    // ================= layer 0: pv = u[m][d] pairs ==========================
    {
        __half2 pv[2][2][2][2];
        #pragma unroll
        for (int tt = 0; tt < 2; ++tt)
            #pragma unroll
            for (int jb = 0; jb < 2; ++jb)
                #pragma unroll
                for (int S = 0; S < 2; ++S)
                    #pragma unroll
                    for (int kh = 0; kh < 2; ++kh)
                        pv[tt][jb][S][kh] =
                            Uhb[(tt * 16 + lq + 8 * jb) * UHSTR +
                                S * 8 + lr + 4 * kh];
        run_block(acc, pv, Ub, 0, wn, lane, lq, lr);
    }

    // ---- epilogue 0: relu -> Ch (fp16 pairs) + d-sum -> out[bg, 0..128) ----
    #pragma unroll
    for (int nt = 0; nt < 8; ++nt) {
        const int n = wn * 64 + nt * 8 + 2 * lr;
        const int col = wn * 32 + nt * 4 + lr;   // n/2
        float s0 = 0.f, s1 = 0.f;
        #pragma unroll
        for (int tt = 0; tt < 2; ++tt) {
            const float v0 = fmaxf(acc[tt][nt][0], 0.f);
            const float v1 = fmaxf(acc[tt][nt][1], 0.f);
            const float v2 = fmaxf(acc[tt][nt][2], 0.f);
            const float v3 = fmaxf(acc[tt][nt][3], 0.f);
            s0 += v0 + v2; s1 += v1 + v3;
            const int d = tt * 16 + lq;
            Chb[d * CHSTR + col]       = __floats2half2_rn(v0, v1);
            Chb[(d + 8) * CHSTR + col] = __floats2half2_rn(v2, v3);
        }
        #pragma unroll
        for (int o = 4; o < 32; o <<= 1) {
            s0 += __shfl_xor_sync(0xffffffffu, s0, o);
            s1 += __shfl_xor_sync(0xffffffffu, s1, o);
        }
        if (lq == 0) {
            out[bg * 256 + n]     = s0;
            out[bg * 256 + n + 1] = s1;
        }
    }
    #pragma unroll
    for (int a = 0; a < 2; ++a)
        #pragma unroll
        for (int b = 0; b < 8; ++b)
            #pragma unroll
            for (int r = 0; r < 4; ++r) acc[a][b][r] = 0.f;
    __syncthreads();   // Ch visible to both n-half warps

    // ================= layer 1: 4 m-blocks, pv = c0[m][d] pairs =============
    for (int mbb = 0; mbb < 4; ++mbb) {
        __half2 pv[2][2][2][2];
        #pragma unroll
        for (int tt = 0; tt < 2; ++tt)
            #pragma unroll
            for (int jb = 0; jb < 2; ++jb)
                #pragma unroll
                for (int S = 0; S < 2; ++S)
                    #pragma unroll
                    for (int kh = 0; kh < 2; ++kh)
                        pv[tt][jb][S][kh] =
                            Chb[(tt * 16 + lq + 8 * jb) * CHSTR +
                                mbb * 16 + S * 8 + lr + 4 * kh];
        run_block(acc, pv, Ub, 32 + mbb * 32, wn, lane, lq, lr);
    }

    // ---- epilogue 1: relu + d-sum -> out[bg, 128..256) ----
    #pragma unroll
    for (int nt = 0; nt < 8; ++nt) {
        const int n = wn * 64 + nt * 8 + 2 * lr;
        float s0 = 0.f, s1 = 0.f;
        #pragma unroll
        for (int tt = 0; tt < 2; ++tt) {
            s0 += fmaxf(acc[tt][nt][0], 0.f) + fmaxf(acc[tt][nt][2], 0.f);
            s1 += fmaxf(acc[tt][nt][1], 0.f) + fmaxf(acc[tt][nt][3], 0.f);
        }
        #pragma unroll
        for (int o = 4; o < 32; o <<= 1) {
            s0 += __shfl_xor_sync(0xffffffffu, s0, o);
            s1 += __shfl_xor_sync(0xffffffffu, s1, o);
        }
        if (lq == 0) {
            out[bg * 256 + 128 + n]     = s0;
            out[bg * 256 + 128 + n + 1] = s1;
        }
    }
}

extern "C" void kernel_launch(void* const* d_in, const int* in_sizes, int n_in,
                              void* d_out, int out_size) {
    const float* x  = (const float*)d_in[0];   // inputs   [4096,32,32]
    const float* w0 = (const float*)d_in[1];   // filter_0 [1,1024,128]
    const float* w1 = (const float*)d_in[2];   // filter_1 [1,4096,128]
    float* out = (float*)d_out;                // [4096, 256]
    (void)in_sizes; (void)n_in; (void)out_size;

    cudaFuncSetAttribute(cin_mma, cudaFuncAttributeMaxDynamicSharedMemorySize,
                         SMEM_BYTES);
    cin_prep<<<(160 * 2048) / 256, 256>>>(w0, w1);
    cin_mma<<<2048, NT, SMEM_BYTES>>>(x, out);
}

// round 17
// speedup vs baseline: 7.4121x; 1.0033x over previous
#include <cuda_runtime.h>
#include <cuda_fp16.h>

// CIN (xDeepFM) fused 2-layer kernel, round 16 — fp16 m16n8k16, N32 warp
// tiles, 1 batch/CTA, 4 CTAs/SM (16 warps/SM).
// B=4096, F=32, D=32, layers [128,128].
//
// GEMM per batch: 32 d-rows x 128 n; K0=1024, K1=4096.
//   z0[d][k=h*32+m]  = u[h][d]*u[m][d]
//   z1[d][k=h*128+m] = u[h][d]*relu(cur0)[m][d]
// fp16 operands, fp32 accumulate. m-side factors pre-packed half2 (Uh at
// staging, relu(c0)->Ch at epilogue 0); h-side factor broadcast per h;
// A fragments = one HMUL2 each. W pre-rounded fp16x2 in exact fragment order
// (n-quartered), read with coalesced LDG.128. No W smem, no mainloop barriers.
// CTA = 1 batch x 4 n-quarter warps (128 thr), warp tile M32 x N32.

typedef unsigned int u32;

// fragment-ordered fp16x2 W: per chunk cc (2048 u32), per wq (512 u32):
// u32 index r = wq*512 + S*256 + j2*128 + lane*4 + c,
// value = {hi = W[k0+1][n], lo = W[k0][n]} fp16,
//   k0 = chunkbase + S*16 + 2*(lane&3) + 8*(c&1),
//   n  = wq*32 + (2*j2 + (c>>1))*8 + (lane>>2).
__device__ __align__(16) u32 g_w[160 * 2048];

namespace {
constexpr int NT     = 128;
constexpr int USTR   = 36;              // Ud [d][h] fp32 stride
constexpr int UHSTR  = 20;              // Uh [d][m2] half2 stride
constexpr int CHSTR  = 68;              // Ch [d][n2] half2 stride
constexpr int UD_SZ  = 32 * USTR;       // 1152 floats
constexpr int UH_SZ  = 32 * UHSTR;      // 640 half2
constexpr int CH_SZ  = 32 * CHSTR;      // 2176 half2
constexpr int UD_BYTES = UD_SZ * 4;                 // 4608
constexpr int UH_BYTES = UH_SZ * 4;                 // 2560
constexpr int CH_BYTES = CH_SZ * 4;                 // 8704
constexpr int SMEM_BYTES = UD_BYTES + UH_BYTES + CH_BYTES;   // 15872
}

__device__ __forceinline__ u32 packh2(float lo, float hi) {
    u32 r;
    asm("cvt.rn.f16x2.f32 %0, %1, %2;" : "=r"(r) : "f"(hi), "f"(lo));
    return r;
}
__device__ __forceinline__ u32 h2u(__half2 v) {
    return *reinterpret_cast<u32*>(&v);
}

// D(16x8,f32) += A(16x16,f16,row) * B(16x8,f16,col)
__device__ __forceinline__ void mma16(float* d, const u32* a, const u32* b) {
    asm volatile(
        "mma.sync.aligned.m16n8k16.row.col.f32.f16.f16.f32 "
        "{%0,%1,%2,%3}, {%4,%5,%6,%7}, {%8,%9}, {%0,%1,%2,%3};"
        : "+f"(d[0]), "+f"(d[1]), "+f"(d[2]), "+f"(d[3])
        : "r"(a[0]), "r"(a[1]), "r"(a[2]), "r"(a[3]), "r"(b[0]), "r"(b[1]));
}

// ---- prep: W -> fragment-ordered fp16x2, n-quartered ------------------------
__global__ __launch_bounds__(256) void cin_prep(const float* __restrict__ w0,
                                                const float* __restrict__ w1) {
    const int i    = blockIdx.x * 256 + threadIdx.x;   // 0 .. 160*2048-1
    const int cc   = i >> 11;
    const int r    = i & 2047;
    const int wq   = r >> 9;
    const int S    = (r >> 8) & 1;
    const int j2   = (r >> 7) & 1;
    const int lane = (r >> 2) & 31;
    const int c    = r & 3;
    const int nt   = 2 * j2 + (c >> 1);
    const int k0   = S * 16 + 2 * (lane & 3) + 8 * (c & 1);
    const int n    = wq * 32 + nt * 8 + (lane >> 2);
    float va, vb;
    if (cc < 32) {
        va = w0[(cc * 32 + k0) * 128 + n];
        vb = w0[(cc * 32 + k0 + 1) * 128 + n];
    } else {
        const int cl = cc - 32, mbb = cl >> 5, h = cl & 31;
        va = w1[(h * 128 + mbb * 32 + k0) * 128 + n];
        vb = w1[(h * 128 + mbb * 32 + k0 + 1) * 128 + n];
    }
    g_w[i] = packh2(va, vb);
}

// ---- one 32-chunk block (fixed m-side half2 fragments pv) -------------------
// pv[tt][jb][S][kh] = half2{ P[m0][d], P[m0+1][d] },
//   m0 = mbase + S*16 + 2lr + 8kh,  d = tt*16 + lq + 8jb.
__device__ __forceinline__ void run_block(
    float acc[2][4][4],
    const __half2 pv[2][2][2][2],
    const float* __restrict__ Ud,     // fp32 U (h-side factor)
    int ccb, int wq, int lane, int lq, int lr)
{
    for (int h = 0; h < 32; ++h) {
        const int cc = ccb + h;
        // per-(chunk, wq) region = 128 float4; per-(S,j2) block = 32 float4
        const float4* wg = reinterpret_cast<const float4*>(g_w) +
                           ((size_t)cc * 4 + wq) * 128 + lane;
        if (cc + 1 < 160) {   // warm L1 for next chunk's 2KB region
            const char* nx = reinterpret_cast<const char*>(
                reinterpret_cast<const float4*>(g_w) +
                ((size_t)(cc + 1) * 4 + wq) * 128);
            asm volatile("prefetch.global.L1 [%0];" :: "l"(nx + lane * 64));
        }
        __half2 um2[2][2];
        #pragma unroll
        for (int tt = 0; tt < 2; ++tt)
            #pragma unroll
            for (int jb = 0; jb < 2; ++jb)
                um2[tt][jb] = __float2half2_rn(
                    Ud[(tt * 16 + lq + 8 * jb) * USTR + h]);

        #pragma unroll
        for (int S = 0; S < 2; ++S) {
            u32 bf[4][2];
            #pragma unroll
            for (int j2 = 0; j2 < 2; ++j2) {
                const float4 wv = __ldg(&wg[(S * 2 + j2) * 32]);
                bf[2 * j2][0]     = __float_as_uint(wv.x);
                bf[2 * j2][1]     = __float_as_uint(wv.y);
                bf[2 * j2 + 1][0] = __float_as_uint(wv.z);
                bf[2 * j2 + 1][1] = __float_as_uint(wv.w);
            }
            u32 ah[2][4];
            #pragma unroll
            for (int tt = 0; tt < 2; ++tt)
                #pragma unroll
                for (int kh = 0; kh < 2; ++kh)
                    #pragma unroll
                    for (int jb = 0; jb < 2; ++jb)
                        ah[tt][kh * 2 + jb] =
                            h2u(__hmul2(um2[tt][jb], pv[tt][jb][S][kh]));
            #pragma unroll
            for (int nt = 0; nt < 4; ++nt)
                #pragma unroll
                for (int tt = 0; tt < 2; ++tt)
                    mma16(acc[tt][nt], ah[tt], bf[nt]);
        }
    }
}

// ---- main -------------------------------------------------------------------
__global__ __launch_bounds__(NT, 4) void cin_mma(
    const float* __restrict__ x,    // [4096, 32, 32]
    float* __restrict__ out)        // [4096, 256]
{
    extern __shared__ __align__(16) char sm[];
    float*   const Ud = reinterpret_cast<float*>(sm);               // [d*36+h]
    __half2* const Uh = reinterpret_cast<__half2*>(sm + UD_BYTES);  // [d*20+m2]
    __half2* const Ch = reinterpret_cast<__half2*>(sm + UD_BYTES + UH_BYTES);

    const int t    = threadIdx.x;
    const int lane = t & 31;
    const int wq   = t >> 5;        // n-quarter: n in [32wq, 32wq+32)
    const int lq   = lane >> 2;
    const int lr   = lane & 3;
    const size_t bg = blockIdx.x;

    // stage this batch's inputs transposed: x[b][h][d] -> Ud[d][h]
    for (int i = t; i < 1024; i += NT) {
        const int h = i >> 5, d = i & 31;
        Ud[d * USTR + h] = x[bg * 1024 + i];
    }
    __syncthreads();
    // pack u into half2 pairs over m: Uh[d][m2] = {u[2m2][d], u[2m2+1][d]}
    for (int e = t; e < 512; e += NT) {
        const int d = e >> 4, m2 = e & 15;
        const float* src = Ud + d * USTR;
        Uh[d * UHSTR + m2] = __floats2half2_rn(src[2 * m2], src[2 * m2 + 1]);
    }
    __syncthreads();

    float acc[2][4][4];
    #pragma unroll
    for (int a = 0; a < 2; ++a)
        #pragma unroll
        for (int b = 0; b < 4; ++b)
            #pragma unroll
            for (int r = 0; r < 4; ++r) acc[a][b][r] = 0.f;

    // ================= layer 0: pv = u[m][d] pairs ==========================
    {
        __half2 pv[2][2][2][2];
        #pragma unroll
        for (int tt = 0; tt < 2; ++tt)
            #pragma unroll
            for (int jb = 0; jb < 2; ++jb)
                #pragma unroll
                for (int S = 0; S < 2; ++S)
                    #pragma unroll
                    for (int kh = 0; kh < 2; ++kh)
                        pv[tt][jb][S][kh] =
                            Uh[(tt * 16 + lq + 8 * jb) * UHSTR +
                               S * 8 + lr + 4 * kh];
        run_block(acc, pv, Ud, 0, wq, lane, lq, lr);
    }

    // ---- epilogue 0: relu -> Ch (fp16 pairs) + d-sum -> out[bg, 0..128) ----
    #pragma unroll
    for (int nt = 0; nt < 4; ++nt) {
        const int n   = wq * 32 + nt * 8 + 2 * lr;
        const int col = wq * 16 + nt * 4 + lr;   // n/2
        float s0 = 0.f, s1 = 0.f;
        #pragma unroll
        for (int tt = 0; tt < 2; ++tt) {
            const float v0 = fmaxf(acc[tt][nt][0], 0.f);
            const float v1 = fmaxf(acc[tt][nt][1], 0.f);
            const float v2 = fmaxf(acc[tt][nt][2], 0.f);
            const float v3 = fmaxf(acc[tt][nt][3], 0.f);
            s0 += v0 + v2; s1 += v1 + v3;
            const int d = tt * 16 + lq;
            Ch[d * CHSTR + col]       = __floats2half2_rn(v0, v1);
            Ch[(d + 8) * CHSTR + col] = __floats2half2_rn(v2, v3);
        }
        #pragma unroll
        for (int o = 4; o < 32; o <<= 1) {
            s0 += __shfl_xor_sync(0xffffffffu, s0, o);
            s1 += __shfl_xor_sync(0xffffffffu, s1, o);
        }
        if (lq == 0) {
            out[bg * 256 + n]     = s0;
            out[bg * 256 + n + 1] = s1;
        }
    }
    #pragma unroll
    for (int a = 0; a < 2; ++a)
        #pragma unroll
        for (int b = 0; b < 4; ++b)
            #pragma unroll
            for (int r = 0; r < 4; ++r) acc[a][b][r] = 0.f;
    __syncthreads();   // Ch visible to all 4 warps

    // ================= layer 1: 4 m-blocks, pv = c0[m][d] pairs =============
    for (int mbb = 0; mbb < 4; ++mbb) {
        __half2 pv[2][2][2][2];
        #pragma unroll
        for (int tt = 0; tt < 2; ++tt)
            #pragma unroll
            for (int jb = 0; jb < 2; ++jb)
                #pragma unroll
                for (int S = 0; S < 2; ++S)
                    #pragma unroll
                    for (int kh = 0; kh < 2; ++kh)
                        pv[tt][jb][S][kh] =
                            Ch[(tt * 16 + lq + 8 * jb) * CHSTR +
                               mbb * 16 + S * 8 + lr + 4 * kh];
        run_block(acc, pv, Ud, 32 + mbb * 32, wq, lane, lq, lr);
    }

    // ---- epilogue 1: relu + d-sum -> out[bg, 128..256) ----
    #pragma unroll
    for (int nt = 0; nt < 4; ++nt) {
        const int n = wq * 32 + nt * 8 + 2 * lr;
        float s0 = 0.f, s1 = 0.f;
        #pragma unroll
        for (int tt = 0; tt < 2; ++tt) {
            s0 += fmaxf(acc[tt][nt][0], 0.f) + fmaxf(acc[tt][nt][2], 0.f);
            s1 += fmaxf(acc[tt][nt][1], 0.f) + fmaxf(acc[tt][nt][3], 0.f);
        }
        #pragma unroll
        for (int o = 4; o < 32; o <<= 1) {
            s0 += __shfl_xor_sync(0xffffffffu, s0, o);
            s1 += __shfl_xor_sync(0xffffffffu, s1, o);
        }
        if (lq == 0) {
            out[bg * 256 + 128 + n]     = s0;
            out[bg * 256 + 128 + n + 1] = s1;
        }
    }
}

extern "C" void kernel_launch(void* const* d_in, const int* in_sizes, int n_in,
                              void* d_out, int out_size) {
    const float* x  = (const float*)d_in[0];   // inputs   [4096,32,32]
    const float* w0 = (const float*)d_in[1];   // filter_0 [1,1024,128]
    const float* w1 = (const float*)d_in[2];   // filter_1 [1,4096,128]
    float* out = (float*)d_out;                // [4096, 256]
    (void)in_sizes; (void)n_in; (void)out_size;

    cudaFuncSetAttribute(cin_mma, cudaFuncAttributeMaxDynamicSharedMemorySize,
                         SMEM_BYTES);
    cin_prep<<<(160 * 2048) / 256, 256>>>(w0, w1);
    cin_mma<<<4096, NT, SMEM_BYTES>>>(x, out);
}